// round 7
// baseline (speedup 1.0000x reference)
#include <cuda_runtime.h>

// Mie scattering, mirrored from the JAX reference.
//  K1 reduce_kernel   : deterministic f64 partial sums of x_i = f32(pi*d_i/wl).
//  K2 mie_coef_kernel : warp-parallel deterministic sum of partials; lane 0
//                       computes spherical Bessel + Mie a_n,b_n in f64 and
//                       emits per-n lane-duplicated f32x2 constants (64B/row):
//                       {P_r,P_i,Q_r,Q_i, -(n+1), n, -(n+1)/n, (2n+1)/n},
//                       P=coeff*(a+b)/2, Q=coeff*(a-b)/2, coeff=(2n+1)/(n(n+1)).
//  K3 intensity_kernel: 2 elements/thread, all math packed f32x2.
//                       Only cos(theta) needed: pi_1 = -1 exactly (the ref's
//                       sqrt(1-c^2)/(sin+eps) == -1 up to its own cancellation
//                       noise). Recurrences:
//                         pcc = c*pi_n
//                         w   = pi_n - (n+1)*pi_{n-1}
//                         u   = pi_n + tau_n      = n*pcc + w
//                         v'  = tau_n - pi_n      = u - 2*pi_n   (= -(pi-tau))
//                         pi_{n+1} = ((2n+1)/n)*pcc - ((n+1)/n)*pi_{n-1}
//                       T1 += P*u, T2 += Q*v'  (sign of T2 irrelevant: |T2|^2)
//                       intensity = (|S1|^2+|S2|^2)/2 == |T1|^2+|T2|^2.

#define NMAX 50
#define EPSV 1e-10

#define RED_BLOCKS 1024
#define RED_THREADS 256

typedef unsigned long long ull;

__device__ double g_partial[RED_BLOCKS];
__device__ __align__(16) ull g_tab[NMAX * 8];   // lane-duplicated f32x2 constants

// ---------------- packed f32x2 helpers ----------------
__device__ __forceinline__ ull splat2(float x) {
    ull r; asm("mov.b64 %0, {%1, %1};" : "=l"(r) : "f"(x)); return r;
}
__device__ __forceinline__ float lane0(ull v) {
    float x, y; asm("mov.b64 {%0, %1}, %2;" : "=f"(x), "=f"(y) : "l"(v)); return x;
}
__device__ __forceinline__ ull mul2(ull a, ull b) {
    ull d; asm("mul.rn.f32x2 %0, %1, %2;" : "=l"(d) : "l"(a), "l"(b)); return d;
}
__device__ __forceinline__ ull add2(ull a, ull b) {
    ull d; asm("add.rn.f32x2 %0, %1, %2;" : "=l"(d) : "l"(a), "l"(b)); return d;
}
__device__ __forceinline__ ull fma2(ull a, ull b, ull c) {
    ull d; asm("fma.rn.f32x2 %0, %1, %2, %3;" : "=l"(d) : "l"(a), "l"(b), "l"(c));
    return d;
}

// ---------------- K1: deterministic partial reduction ----------------
__global__ void reduce_kernel(const float* __restrict__ d, int n) {
    __shared__ double sh[RED_THREADS];
    const float PI_F = 3.14159274101257324f;   // f32(pi)
    const float WL_F = 5.5e-07f;
    double acc = 0.0;
    for (int i = blockIdx.x * blockDim.x + threadIdx.x; i < n;
         i += gridDim.x * blockDim.x) {
        float x = __fdiv_rn(__fmul_rn(PI_F, d[i]), WL_F);
        acc += (double)x;
    }
    sh[threadIdx.x] = acc;
    __syncthreads();
    for (int s = RED_THREADS / 2; s > 0; s >>= 1) {
        if (threadIdx.x < s) sh[threadIdx.x] += sh[threadIdx.x + s];
        __syncthreads();
    }
    if (threadIdx.x == 0) g_partial[blockIdx.x] = sh[0];
}

// ---------------- K2: scalar Mie coefficients (f64) ----------------
__device__ __forceinline__ ull dupf(double v) {
    unsigned int b = __float_as_uint((float)v);
    return ((ull)b << 32) | (ull)b;
}

__global__ void mie_coef_kernel(int n_total) {
    if (blockIdx.x != 0 || threadIdx.x >= 32) return;
    int lane = threadIdx.x;

    // deterministic warp-parallel sum: fixed slices + fixed shuffle tree
    double acc = 0.0;
    for (int i = lane; i < RED_BLOCKS; i += 32) acc += g_partial[i];
    #pragma unroll
    for (int off = 16; off > 0; off >>= 1)
        acc += __shfl_down_sync(0xffffffffu, acc, off);
    if (lane != 0) return;
    double s = acc;

    float xm_f = (float)(s / (double)n_total);   // f32 x_mean (as reference sees)
    double x  = (double)xm_f;
    float mx_f = __fmul_rn(1.31f, xm_f);         // mirror f32 m*x promotion
    double mx = (double)mx_f;
    double m  = (double)1.31f;

    double invx  = 1.0 / x;
    double invmx = 1.0 / mx;
    double invm  = 1.0 / m;

    double jx[NMAX + 1], yx[NMAX + 1], jmx[NMAX + 1];

    double sx = sin(x), cx = cos(x);
    jx[0] = sx * invx;
    jx[1] = sx * invx * invx - cx * invx;
    yx[0] = -cx * invx;
    yx[1] = -cx * invx * invx - sx * invx;

    double smx = sin(mx), cmx = cos(mx);
    jmx[0] = smx * invmx;
    jmx[1] = smx * invmx * invmx - cmx * invmx;

    for (int n = 1; n < NMAX; n++) {
        double cX = (2.0 * n + 1.0) * invx;
        double cM = (2.0 * n + 1.0) * invmx;
        jx[n + 1]  = cX * jx[n]  - jx[n - 1];
        yx[n + 1]  = cX * yx[n]  - yx[n - 1];
        jmx[n + 1] = cM * jmx[n] - jmx[n - 1];
    }

    for (int n = 1; n <= NMAX; n++) {
        double nn = (double)n;
        double djn = jmx[n - 1] - (nn + 1.0) * invmx * jmx[n];
        double D = djn / (jmx[n] + EPSV);

        double psi  = x * jx[n];
        double psi1 = x * jx[n - 1];
        double xiR  = x * jx[n],     xiI  = x * yx[n];
        double xi1R = x * jx[n - 1], xi1I = x * yx[n - 1];

        double nox = nn * invx;
        double fa = D * invm + nox;
        double fb = m * D + nox;

        double numA = fa * psi - psi1;
        double dAR = fa * xiR - xi1R + EPSV;
        double dAI = fa * xiI - xi1I;
        double rA = numA / (dAR * dAR + dAI * dAI);
        double aR =  rA * dAR;
        double aI = -rA * dAI;

        double numB = fb * psi - psi1;
        double dBR = fb * xiR - xi1R + EPSV;
        double dBI = fb * xiI - xi1I;
        double rB = numB / (dBR * dBR + dBI * dBI);
        double bR =  rB * dBR;
        double bI = -rB * dBI;

        double coeff = (2.0 * nn + 1.0) / (nn * (nn + 1.0));
        ull* row = &g_tab[(n - 1) * 8];
        row[0] = dupf(0.5 * coeff * (aR + bR));   // P_r
        row[1] = dupf(0.5 * coeff * (aI + bI));   // P_i
        row[2] = dupf(0.5 * coeff * (aR - bR));   // Q_r
        row[3] = dupf(0.5 * coeff * (aI - bI));   // Q_i
        row[4] = dupf(-(nn + 1.0));               // w :  -(n+1)
        row[5] = dupf(nn);                        // u :  n
        row[6] = dupf(-(nn + 1.0) / nn);          // pin: -(n+1)/n
        row[7] = dupf((2.0 * nn + 1.0) / nn);     // pin: (2n+1)/n
    }
}

// ---------------- packed per-pair scattering recurrence ----------------
__device__ __forceinline__ ull mie_pair(ull th2, const ull* __restrict__ tab) {
    const ull kneg1 = splat2(-1.0f);
    const ull kneg2 = splat2(-2.0f);

    // cos(th) = sin(pi/2 - th); pi/2 = PIO2_HI + (-4.37113883e-8)
    ull r = fma2(th2, kneg1, splat2(1.57079637050628662109375f)); // PIO2_HI - th
    r = add2(r, splat2(-4.37113883e-8f));                          // pi/2 - th

    // flag-immune Taylor sin on [-pi/2, pi/2]
    ull u2 = mul2(r, r);
    ull p  = splat2(1.60590438368e-10f);                 //  1/13!
    p = fma2(p, u2, splat2(-2.50521083854e-8f));         // -1/11!
    p = fma2(p, u2, splat2(2.75573192240e-6f));          //  1/9!
    p = fma2(p, u2, splat2(-1.98412698413e-4f));         // -1/7!
    p = fma2(p, u2, splat2(8.33333333333e-3f));          //  1/5!
    p = fma2(p, u2, splat2(-1.66666666667e-1f));         // -1/3!
    ull c = fma2(mul2(p, u2), r, r);                     // c = cos(th)

    // n = 1: tau_1 = c (reference hardcodes), pi_1 = -1 exactly.
    ull pi_p = kneg1;                          // pi_1
    ull pi_c = mul2(c, splat2(-3.0f));         // pi_2 = 3*c*pi_1
    ull u1  = add2(c, kneg1);                  // pi_1 + tau_1 = c - 1
    ull vp1 = add2(c, splat2(1.0f));           // tau_1 - pi_1 = c + 1

    const ulonglong2* row0 = (const ulonglong2*)tab;
    ulonglong2 pq0 = row0[0];                  // {P_r, P_i}
    ulonglong2 pq1 = row0[1];                  // {Q_r, Q_i}
    ull T1r = mul2(pq0.x, u1);
    ull T1i = mul2(pq0.y, u1);
    ull T2r = mul2(pq1.x, vp1);
    ull T2i = mul2(pq1.y, vp1);

#pragma unroll
    for (int nn = 2; nn <= NMAX; nn++) {
        const ulonglong2* rw = (const ulonglong2*)&tab[(nn - 1) * 8];
        ulonglong2 a  = rw[0];                // {P_r, P_i}
        ulonglong2 b  = rw[1];                // {Q_r, Q_i}
        ulonglong2 k0 = rw[2];                // {-(n+1), n}
        ulonglong2 k1 = rw[3];                // {-(n+1)/n, (2n+1)/n}

        ull pcc = mul2(c, pi_c);              // c * pi_n
        ull w   = fma2(k0.x, pi_p, pi_c);     // pi_n - (n+1)*pi_{n-1}
        ull u   = fma2(k0.y, pcc, w);         // pi_n + tau_n
        ull vp  = fma2(kneg2, pi_c, u);       // tau_n - pi_n  (exact -2*pi_c)
        ull t2  = mul2(k1.x, pi_p);           // -((n+1)/n)*pi_{n-1}
        ull pin = fma2(k1.y, pcc, t2);        // pi_{n+1}

        T1r = fma2(a.x, u, T1r);
        T1i = fma2(a.y, u, T1i);
        T2r = fma2(b.x, vp, T2r);             // accumulates -(Q*(pi-tau));
        T2i = fma2(b.y, vp, T2i);             // sign dies in |T2|^2

        pi_p = pi_c;
        pi_c = pin;
    }

    // (|S1|^2 + |S2|^2)/2 == |T1|^2 + |T2|^2 ; then * wl^2/(4 pi^2)
    ull I = fma2(T1r, T1r, fma2(T1i, T1i, fma2(T2r, T2r, mul2(T2i, T2i))));
    const float SCALE = (float)(3.0249999999999994e-13 / 39.47841760435743);
    return mul2(I, splat2(SCALE));
}

// ---------------- K3: 2 elements per thread ----------------
__global__ void __launch_bounds__(256)
intensity_kernel(const float* __restrict__ theta, float* __restrict__ out, int n) {
    __shared__ __align__(16) ull sh_tab[NMAX * 8];
    int t = threadIdx.x;
    for (int k = t; k < NMAX * 8; k += 256) sh_tab[k] = g_tab[k];
    __syncthreads();

    int pairs = n >> 1;
    int i = blockIdx.x * 256 + t;
    if (i < pairs) {
        ull th2 = ((const ull*)theta)[i];
        ((ull*)out)[i] = mie_pair(th2, sh_tab);
    }
    // odd tail (not hit for 8*768*768, kept for safety)
    if ((n & 1) && i == 0) {
        ull th2 = splat2(theta[n - 1]);
        out[n - 1] = lane0(mie_pair(th2, sh_tab));
    }
}

extern "C" void kernel_launch(void* const* d_in, const int* in_sizes, int n_in,
                              void* d_out, int out_size) {
    const float* d_diam  = (const float*)d_in[0];
    const float* d_theta = (const float*)d_in[1];
    float* out = (float*)d_out;
    int n = in_sizes[0];

    reduce_kernel<<<RED_BLOCKS, RED_THREADS>>>(d_diam, n);
    mie_coef_kernel<<<1, 32>>>(n);
    int pairs = (n >> 1);
    int blocks = (pairs + 255) / 256;
    if (blocks < 1) blocks = 1;
    intensity_kernel<<<blocks, 256>>>(d_theta, out, n);
}

// round 13
// speedup vs baseline: 2.0040x; 2.0040x over previous
#include <cuda_runtime.h>

// Mie scattering, mirrored from the JAX reference.
//  K1 reduce_kernel   : deterministic f64 partial sums of x_i = f32(pi*d_i/wl),
//                       float4 loads + 4 independent accumulators (ILP/MLP).
//  K2 mie_coef_kernel : warp-sum of partials; lane 0 runs the serial Bessel
//                       recurrences (f64) into shared; 50 threads then compute
//                       a_n/b_n in parallel (divides pipeline across lanes) and
//                       emit per-n lane-duplicated f32x2 constants (64B/row):
//                       {P_r,P_i,Q_r,Q_i, -(n+1), n, -(n+1)/n, (2n+1)/n},
//                       P=coeff*(a+b)/2, Q=coeff*(a-b)/2, coeff=(2n+1)/(n(n+1)).
//  K3 intensity_kernel: 2 elements/thread, all math packed f32x2.
//                       Only cos(theta) needed: pi_1 = -1 exactly. Recurrences:
//                         pcc = c*pi_n
//                         w   = pi_n - (n+1)*pi_{n-1}
//                         u   = pi_n + tau_n      = n*pcc + w
//                         v'  = tau_n - pi_n      = u - 2*pi_n
//                         pi_{n+1} = ((2n+1)/n)*pcc - ((n+1)/n)*pi_{n-1}
//                       T1 += P*u, T2 += Q*v'  (sign of T2 dies in |T2|^2)
//                       intensity = (|S1|^2+|S2|^2)/2 == |T1|^2+|T2|^2.

#define NMAX 50
#define EPSV 1e-10

#define RED_BLOCKS 1024
#define RED_THREADS 256

typedef unsigned long long ull;

__device__ double g_partial[RED_BLOCKS];
__device__ __align__(16) ull g_tab[NMAX * 8];   // lane-duplicated f32x2 constants

// ---------------- packed f32x2 helpers ----------------
__device__ __forceinline__ ull splat2(float x) {
    ull r; asm("mov.b64 %0, {%1, %1};" : "=l"(r) : "f"(x)); return r;
}
__device__ __forceinline__ float lane0(ull v) {
    float x, y; asm("mov.b64 {%0, %1}, %2;" : "=f"(x), "=f"(y) : "l"(v)); return x;
}
__device__ __forceinline__ ull mul2(ull a, ull b) {
    ull d; asm("mul.rn.f32x2 %0, %1, %2;" : "=l"(d) : "l"(a), "l"(b)); return d;
}
__device__ __forceinline__ ull add2(ull a, ull b) {
    ull d; asm("add.rn.f32x2 %0, %1, %2;" : "=l"(d) : "l"(a), "l"(b)); return d;
}
__device__ __forceinline__ ull fma2(ull a, ull b, ull c) {
    ull d; asm("fma.rn.f32x2 %0, %1, %2, %3;" : "=l"(d) : "l"(a), "l"(b), "l"(c));
    return d;
}

__device__ __forceinline__ float xmap(float di) {
    const float PI_F = 3.14159274101257324f;   // f32(pi)
    const float WL_F = 5.5e-07f;
    return __fdiv_rn(__fmul_rn(PI_F, di), WL_F);
}

// ---------------- K1: deterministic partial reduction (float4 + 4 accs) ------
__global__ void reduce_kernel(const float* __restrict__ d, int n) {
    __shared__ double sh[RED_THREADS];
    int n4 = n >> 2;
    const float4* d4 = (const float4*)d;
    double a0 = 0.0, a1 = 0.0, a2 = 0.0, a3 = 0.0;
    for (int i = blockIdx.x * blockDim.x + threadIdx.x; i < n4;
         i += gridDim.x * blockDim.x) {
        float4 v = d4[i];
        a0 += (double)xmap(v.x);
        a1 += (double)xmap(v.y);
        a2 += (double)xmap(v.z);
        a3 += (double)xmap(v.w);
    }
    double acc = (a0 + a1) + (a2 + a3);
    if (blockIdx.x == 0 && threadIdx.x == 0) {        // deterministic tail
        for (int i = n4 << 2; i < n; i++) acc += (double)xmap(d[i]);
    }
    sh[threadIdx.x] = acc;
    __syncthreads();
    for (int s = RED_THREADS / 2; s > 0; s >>= 1) {
        if (threadIdx.x < s) sh[threadIdx.x] += sh[threadIdx.x + s];
        __syncthreads();
    }
    if (threadIdx.x == 0) g_partial[blockIdx.x] = sh[0];
}

// ---------------- K2: Mie coefficients (serial recurrence + parallel a/b) ----
__device__ __forceinline__ ull dupf(double v) {
    unsigned int b = __float_as_uint((float)v);
    return ((ull)b << 32) | (ull)b;
}

__global__ void mie_coef_kernel(int n_total) {   // <<<1, 64>>>
    __shared__ double s_jx[NMAX + 1], s_yx[NMAX + 1], s_jmx[NMAX + 1];
    __shared__ double s_c[4];   // x, mx, invx, invmx
    int tid = threadIdx.x;

    if (tid < 32) {
        // deterministic warp-parallel sum: fixed slices + fixed shuffle tree
        double acc = 0.0;
        for (int i = tid; i < RED_BLOCKS; i += 32) acc += g_partial[i];
        #pragma unroll
        for (int off = 16; off > 0; off >>= 1)
            acc += __shfl_down_sync(0xffffffffu, acc, off);

        if (tid == 0) {
            float xm_f = (float)(acc / (double)n_total);  // f32 x_mean
            double x  = (double)xm_f;
            float mx_f = __fmul_rn(1.31f, xm_f);          // mirror f32 m*x
            double mx = (double)mx_f;

            double invx  = 1.0 / x;
            double invmx = 1.0 / mx;
            s_c[0] = x; s_c[1] = mx; s_c[2] = invx; s_c[3] = invmx;

            double sx = sin(x), cx = cos(x);
            s_jx[0] = sx * invx;
            s_jx[1] = sx * invx * invx - cx * invx;
            s_yx[0] = -cx * invx;
            s_yx[1] = -cx * invx * invx - sx * invx;

            double smx = sin(mx), cmx = cos(mx);
            s_jmx[0] = smx * invmx;
            s_jmx[1] = smx * invmx * invmx - cmx * invmx;

            // three independent 50-step recurrences (short serial part)
            for (int n = 1; n < NMAX; n++) {
                double cX = (2.0 * n + 1.0) * invx;
                double cM = (2.0 * n + 1.0) * invmx;
                s_jx[n + 1]  = cX * s_jx[n]  - s_jx[n - 1];
                s_yx[n + 1]  = cX * s_yx[n]  - s_yx[n - 1];
                s_jmx[n + 1] = cM * s_jmx[n] - s_jmx[n - 1];
            }
        }
    }
    __syncthreads();

    if (tid < NMAX) {
        int n = tid + 1;
        double nn = (double)n;
        double x = s_c[0], invx = s_c[2], invmx = s_c[3];
        const double m = (double)1.31f;
        const double invm = 1.0 / m;

        double jn  = s_jx[n],  jn1 = s_jx[n - 1];
        double yn  = s_yx[n],  yn1 = s_yx[n - 1];
        double jmn = s_jmx[n], jmn1 = s_jmx[n - 1];

        double djn = jmn1 - (nn + 1.0) * invmx * jmn;
        double D = djn / (jmn + EPSV);

        double psi  = x * jn;
        double psi1 = x * jn1;
        double xiR  = x * jn,  xiI  = x * yn;
        double xi1R = x * jn1, xi1I = x * yn1;

        double nox = nn * invx;
        double fa = D * invm + nox;
        double fb = m * D + nox;

        double numA = fa * psi - psi1;
        double dAR = fa * xiR - xi1R + EPSV;
        double dAI = fa * xiI - xi1I;
        double rA = numA / (dAR * dAR + dAI * dAI);
        double aR =  rA * dAR;
        double aI = -rA * dAI;

        double numB = fb * psi - psi1;
        double dBR = fb * xiR - xi1R + EPSV;
        double dBI = fb * xiI - xi1I;
        double rB = numB / (dBR * dBR + dBI * dBI);
        double bR =  rB * dBR;
        double bI = -rB * dBI;

        double coeff = (2.0 * nn + 1.0) / (nn * (nn + 1.0));
        ull* row = &g_tab[tid * 8];
        row[0] = dupf(0.5 * coeff * (aR + bR));   // P_r
        row[1] = dupf(0.5 * coeff * (aI + bI));   // P_i
        row[2] = dupf(0.5 * coeff * (aR - bR));   // Q_r
        row[3] = dupf(0.5 * coeff * (aI - bI));   // Q_i
        row[4] = dupf(-(nn + 1.0));               // w :  -(n+1)
        row[5] = dupf(nn);                        // u :  n
        row[6] = dupf(-(nn + 1.0) / nn);          // pin: -(n+1)/n
        row[7] = dupf((2.0 * nn + 1.0) / nn);     // pin: (2n+1)/n
    }
}

// ---------------- packed per-pair scattering recurrence ----------------
__device__ __forceinline__ ull mie_pair(ull th2, const ull* __restrict__ tab) {
    const ull kneg1 = splat2(-1.0f);
    const ull kneg2 = splat2(-2.0f);

    // cos(th) = sin(pi/2 - th); pi/2 = PIO2_HI + (-4.37113883e-8)
    ull r = fma2(th2, kneg1, splat2(1.57079637050628662109375f)); // PIO2_HI - th
    r = add2(r, splat2(-4.37113883e-8f));                          // pi/2 - th

    // flag-immune Taylor sin on [-pi/2, pi/2]
    ull u2 = mul2(r, r);
    ull p  = splat2(1.60590438368e-10f);                 //  1/13!
    p = fma2(p, u2, splat2(-2.50521083854e-8f));         // -1/11!
    p = fma2(p, u2, splat2(2.75573192240e-6f));          //  1/9!
    p = fma2(p, u2, splat2(-1.98412698413e-4f));         // -1/7!
    p = fma2(p, u2, splat2(8.33333333333e-3f));          //  1/5!
    p = fma2(p, u2, splat2(-1.66666666667e-1f));         // -1/3!
    ull c = fma2(mul2(p, u2), r, r);                     // c = cos(th)

    // n = 1: tau_1 = c (reference hardcodes), pi_1 = -1 exactly.
    ull pi_p = kneg1;                          // pi_1
    ull pi_c = mul2(c, splat2(-3.0f));         // pi_2 = 3*c*pi_1
    ull u1  = add2(c, kneg1);                  // pi_1 + tau_1 = c - 1
    ull vp1 = add2(c, splat2(1.0f));           // tau_1 - pi_1 = c + 1

    const ulonglong2* row0 = (const ulonglong2*)tab;
    ulonglong2 pq0 = row0[0];                  // {P_r, P_i}
    ulonglong2 pq1 = row0[1];                  // {Q_r, Q_i}
    ull T1r = mul2(pq0.x, u1);
    ull T1i = mul2(pq0.y, u1);
    ull T2r = mul2(pq1.x, vp1);
    ull T2i = mul2(pq1.y, vp1);

#pragma unroll
    for (int nn = 2; nn <= NMAX; nn++) {
        const ulonglong2* rw = (const ulonglong2*)&tab[(nn - 1) * 8];
        ulonglong2 a  = rw[0];                // {P_r, P_i}
        ulonglong2 b  = rw[1];                // {Q_r, Q_i}
        ulonglong2 k0 = rw[2];                // {-(n+1), n}
        ulonglong2 k1 = rw[3];                // {-(n+1)/n, (2n+1)/n}

        ull pcc = mul2(c, pi_c);              // c * pi_n
        ull w   = fma2(k0.x, pi_p, pi_c);     // pi_n - (n+1)*pi_{n-1}
        ull u   = fma2(k0.y, pcc, w);         // pi_n + tau_n
        ull vp  = fma2(kneg2, pi_c, u);       // tau_n - pi_n  (exact -2*pi_c)
        ull t2  = mul2(k1.x, pi_p);           // -((n+1)/n)*pi_{n-1}
        ull pin = fma2(k1.y, pcc, t2);        // pi_{n+1}

        T1r = fma2(a.x, u, T1r);
        T1i = fma2(a.y, u, T1i);
        T2r = fma2(b.x, vp, T2r);             // accumulates -(Q*(pi-tau));
        T2i = fma2(b.y, vp, T2i);             // sign dies in |T2|^2

        pi_p = pi_c;
        pi_c = pin;
    }

    // (|S1|^2 + |S2|^2)/2 == |T1|^2 + |T2|^2 ; then * wl^2/(4 pi^2)
    ull I = fma2(T1r, T1r, fma2(T1i, T1i, fma2(T2r, T2r, mul2(T2i, T2i))));
    const float SCALE = (float)(3.0249999999999994e-13 / 39.47841760435743);
    return mul2(I, splat2(SCALE));
}

// ---------------- K3: 2 elements per thread ----------------
__global__ void __launch_bounds__(256)
intensity_kernel(const float* __restrict__ theta, float* __restrict__ out, int n) {
    __shared__ __align__(16) ull sh_tab[NMAX * 8];
    int t = threadIdx.x;
    for (int k = t; k < NMAX * 8; k += 256) sh_tab[k] = g_tab[k];
    __syncthreads();

    int pairs = n >> 1;
    int i = blockIdx.x * 256 + t;
    if (i < pairs) {
        ull th2 = ((const ull*)theta)[i];
        ((ull*)out)[i] = mie_pair(th2, sh_tab);
    }
    // odd tail (not hit for 8*768*768, kept for safety)
    if ((n & 1) && i == 0) {
        ull th2 = splat2(theta[n - 1]);
        out[n - 1] = lane0(mie_pair(th2, sh_tab));
    }
}

extern "C" void kernel_launch(void* const* d_in, const int* in_sizes, int n_in,
                              void* d_out, int out_size) {
    const float* d_diam  = (const float*)d_in[0];
    const float* d_theta = (const float*)d_in[1];
    float* out = (float*)d_out;
    int n = in_sizes[0];

    reduce_kernel<<<RED_BLOCKS, RED_THREADS>>>(d_diam, n);
    mie_coef_kernel<<<1, 64>>>(n);
    int pairs = (n >> 1);
    int blocks = (pairs + 255) / 256;
    if (blocks < 1) blocks = 1;
    intensity_kernel<<<blocks, 256>>>(d_theta, out, n);
}

// round 14
// speedup vs baseline: 2.3462x; 1.1707x over previous
#include <cuda_runtime.h>

// Mie scattering, mirrored from the JAX reference.
//  K1 reduce_kernel   : deterministic f64 partial sums of raw d_i (no divide;
//                       x_mean = pi_f32*mean(d)/wl_f32 is formed once in K2 —
//                       per-element f32 rounding of x_i averages out to ~2e-4
//                       of one x_mean ulp, statistically invisible).
//  K2 mie_coef_kernel : warp-sum of partials; lane 0 runs the serial Bessel
//                       recurrences (f64) into shared; 50 threads compute
//                       a_n/b_n in parallel and emit per-n lane-duplicated
//                       f32x2 constants (32B/row): {P_r,P_i,Q_r,Q_i},
//                       P=coeff*(a+b)/2, Q=coeff*(a-b)/2, coeff=(2n+1)/(n(n+1)).
//  K3 intensity_kernel: 2 elements/thread, packed f32x2; per-n recurrence
//                       constants are compile-time splats (no LDS for them).
//                       Only cos(theta) needed: pi_1 = -1 exactly. Recurrences:
//                         pcc = c*pi_n
//                         w   = pi_n - (n+1)*pi_{n-1}
//                         u   = pi_n + tau_n      = n*pcc + w
//                         v'  = tau_n - pi_n      = u - 2*pi_n
//                         pi_{n+1} = ((2n+1)/n)*pcc - ((n+1)/n)*pi_{n-1}
//                       T1 += P*u, T2 += Q*v'  (sign of T2 dies in |T2|^2)
//                       intensity = (|S1|^2+|S2|^2)/2 == |T1|^2+|T2|^2.

#define NMAX 50
#define EPSV 1e-10

#define RED_BLOCKS 1024
#define RED_THREADS 256

typedef unsigned long long ull;

__device__ double g_partial[RED_BLOCKS];
__device__ __align__(16) ull g_tab[NMAX * 4];   // {P_r,P_i,Q_r,Q_i} per n

// ---------------- packed f32x2 helpers ----------------
__device__ __forceinline__ ull splat2(float x) {
    ull r; asm("mov.b64 %0, {%1, %1};" : "=l"(r) : "f"(x)); return r;
}
__device__ __forceinline__ float lane0(ull v) {
    float x, y; asm("mov.b64 {%0, %1}, %2;" : "=f"(x), "=f"(y) : "l"(v)); return x;
}
__device__ __forceinline__ ull mul2(ull a, ull b) {
    ull d; asm("mul.rn.f32x2 %0, %1, %2;" : "=l"(d) : "l"(a), "l"(b)); return d;
}
__device__ __forceinline__ ull add2(ull a, ull b) {
    ull d; asm("add.rn.f32x2 %0, %1, %2;" : "=l"(d) : "l"(a), "l"(b)); return d;
}
__device__ __forceinline__ ull fma2(ull a, ull b, ull c) {
    ull d; asm("fma.rn.f32x2 %0, %1, %2, %3;" : "=l"(d) : "l"(a), "l"(b), "l"(c));
    return d;
}

// ---------------- K1: deterministic partial reduction of raw d ----------
__global__ void reduce_kernel(const float* __restrict__ d, int n) {
    __shared__ double sh[RED_THREADS];
    int n4 = n >> 2;
    const float4* d4 = (const float4*)d;
    double a0 = 0.0, a1 = 0.0, a2 = 0.0, a3 = 0.0;
    for (int i = blockIdx.x * blockDim.x + threadIdx.x; i < n4;
         i += gridDim.x * blockDim.x) {
        float4 v = d4[i];
        a0 += (double)v.x;
        a1 += (double)v.y;
        a2 += (double)v.z;
        a3 += (double)v.w;
    }
    double acc = (a0 + a1) + (a2 + a3);
    if (blockIdx.x == 0 && threadIdx.x == 0) {        // deterministic tail
        for (int i = n4 << 2; i < n; i++) acc += (double)d[i];
    }
    sh[threadIdx.x] = acc;
    __syncthreads();
    for (int s = RED_THREADS / 2; s > 0; s >>= 1) {
        if (threadIdx.x < s) sh[threadIdx.x] += sh[threadIdx.x + s];
        __syncthreads();
    }
    if (threadIdx.x == 0) g_partial[blockIdx.x] = sh[0];
}

// ---------------- K2: Mie coefficients (serial recurrence + parallel a/b) ----
__device__ __forceinline__ ull dupf(double v) {
    unsigned int b = __float_as_uint((float)v);
    return ((ull)b << 32) | (ull)b;
}

__global__ void mie_coef_kernel(int n_total) {   // <<<1, 64>>>
    __shared__ double s_jx[NMAX + 1], s_yx[NMAX + 1], s_jmx[NMAX + 1];
    __shared__ double s_c[4];   // x, mx, invx, invmx
    int tid = threadIdx.x;

    if (tid < 32) {
        // deterministic warp-parallel sum: fixed slices + fixed shuffle tree
        double acc = 0.0;
        for (int i = tid; i < RED_BLOCKS; i += 32) acc += g_partial[i];
        #pragma unroll
        for (int off = 16; off > 0; off >>= 1)
            acc += __shfl_down_sync(0xffffffffu, acc, off);

        if (tid == 0) {
            const double PI_D = (double)3.14159274101257324f;  // f64 of f32(pi)
            const double WL_D = (double)5.5e-07f;              // f64 of f32(wl)
            double mean_d = acc / (double)n_total;
            float xm_f = (float)(PI_D * mean_d / WL_D);        // f32 x_mean
            double x  = (double)xm_f;
            float mx_f = __fmul_rn(1.31f, xm_f);               // mirror f32 m*x
            double mx = (double)mx_f;

            double invx  = 1.0 / x;
            double invmx = 1.0 / mx;
            s_c[0] = x; s_c[1] = mx; s_c[2] = invx; s_c[3] = invmx;

            double sx = sin(x), cx = cos(x);
            s_jx[0] = sx * invx;
            s_jx[1] = sx * invx * invx - cx * invx;
            s_yx[0] = -cx * invx;
            s_yx[1] = -cx * invx * invx - sx * invx;

            double smx = sin(mx), cmx = cos(mx);
            s_jmx[0] = smx * invmx;
            s_jmx[1] = smx * invmx * invmx - cmx * invmx;

            // three independent 50-step recurrences (short serial part)
            for (int n = 1; n < NMAX; n++) {
                double cX = (2.0 * n + 1.0) * invx;
                double cM = (2.0 * n + 1.0) * invmx;
                s_jx[n + 1]  = cX * s_jx[n]  - s_jx[n - 1];
                s_yx[n + 1]  = cX * s_yx[n]  - s_yx[n - 1];
                s_jmx[n + 1] = cM * s_jmx[n] - s_jmx[n - 1];
            }
        }
    }
    __syncthreads();

    if (tid < NMAX) {
        int n = tid + 1;
        double nn = (double)n;
        double x = s_c[0], invx = s_c[2], invmx = s_c[3];
        const double m = (double)1.31f;
        const double invm = 1.0 / m;

        double jn  = s_jx[n],  jn1 = s_jx[n - 1];
        double yn  = s_yx[n],  yn1 = s_yx[n - 1];
        double jmn = s_jmx[n], jmn1 = s_jmx[n - 1];

        double djn = jmn1 - (nn + 1.0) * invmx * jmn;
        double D = djn / (jmn + EPSV);

        double psi  = x * jn;
        double psi1 = x * jn1;
        double xiR  = x * jn,  xiI  = x * yn;
        double xi1R = x * jn1, xi1I = x * yn1;

        double nox = nn * invx;
        double fa = D * invm + nox;
        double fb = m * D + nox;

        double numA = fa * psi - psi1;
        double dAR = fa * xiR - xi1R + EPSV;
        double dAI = fa * xiI - xi1I;
        double rA = numA / (dAR * dAR + dAI * dAI);
        double aR =  rA * dAR;
        double aI = -rA * dAI;

        double numB = fb * psi - psi1;
        double dBR = fb * xiR - xi1R + EPSV;
        double dBI = fb * xiI - xi1I;
        double rB = numB / (dBR * dBR + dBI * dBI);
        double bR =  rB * dBR;
        double bI = -rB * dBI;

        double coeff = (2.0 * nn + 1.0) / (nn * (nn + 1.0));
        ull* row = &g_tab[tid * 4];
        row[0] = dupf(0.5 * coeff * (aR + bR));   // P_r
        row[1] = dupf(0.5 * coeff * (aI + bI));   // P_i
        row[2] = dupf(0.5 * coeff * (aR - bR));   // Q_r
        row[3] = dupf(0.5 * coeff * (aI - bI));   // Q_i
    }
}

// ---------------- packed per-pair scattering recurrence ----------------
__device__ __forceinline__ ull mie_pair(ull th2, const ull* __restrict__ tab) {
    const ull kneg1 = splat2(-1.0f);
    const ull kneg2 = splat2(-2.0f);

    // cos(th) = sin(pi/2 - th); pi/2 = PIO2_HI + (-4.37113883e-8)
    ull r = fma2(th2, kneg1, splat2(1.57079637050628662109375f)); // PIO2_HI - th
    r = add2(r, splat2(-4.37113883e-8f));                          // pi/2 - th

    // flag-immune Taylor sin on [-pi/2, pi/2]
    ull u2 = mul2(r, r);
    ull p  = splat2(1.60590438368e-10f);                 //  1/13!
    p = fma2(p, u2, splat2(-2.50521083854e-8f));         // -1/11!
    p = fma2(p, u2, splat2(2.75573192240e-6f));          //  1/9!
    p = fma2(p, u2, splat2(-1.98412698413e-4f));         // -1/7!
    p = fma2(p, u2, splat2(8.33333333333e-3f));          //  1/5!
    p = fma2(p, u2, splat2(-1.66666666667e-1f));         // -1/3!
    ull c = fma2(mul2(p, u2), r, r);                     // c = cos(th)

    // n = 1: tau_1 = c (reference hardcodes), pi_1 = -1 exactly.
    ull pi_p = kneg1;                          // pi_1
    ull pi_c = mul2(c, splat2(-3.0f));         // pi_2 = 3*c*pi_1
    ull u1  = add2(c, kneg1);                  // pi_1 + tau_1 = c - 1
    ull vp1 = add2(c, splat2(1.0f));           // tau_1 - pi_1 = c + 1

    const ulonglong2* row0 = (const ulonglong2*)tab;
    ulonglong2 pq0 = row0[0];                  // {P_r, P_i}
    ulonglong2 pq1 = row0[1];                  // {Q_r, Q_i}
    ull T1r = mul2(pq0.x, u1);
    ull T1i = mul2(pq0.y, u1);
    ull T2r = mul2(pq1.x, vp1);
    ull T2i = mul2(pq1.y, vp1);

#pragma unroll
    for (int nn = 2; nn <= NMAX; nn++) {
        const float fn = (float)nn;
        const ulonglong2* rw = (const ulonglong2*)&tab[(nn - 1) * 4];
        ulonglong2 a  = rw[0];                // {P_r, P_i}
        ulonglong2 b  = rw[1];                // {Q_r, Q_i}

        // compile-time per-n constants (warp-uniform; no LDS)
        ull kw  = splat2(-(fn + 1.0f));       // -(n+1)
        ull ku  = splat2(fn);                 // n
        ull kp1 = splat2(-(fn + 1.0f) / fn);  // -(n+1)/n
        ull kp2 = splat2((2.0f * fn + 1.0f) / fn); // (2n+1)/n

        ull pcc = mul2(c, pi_c);              // c * pi_n
        ull w   = fma2(kw, pi_p, pi_c);       // pi_n - (n+1)*pi_{n-1}
        ull u   = fma2(ku, pcc, w);           // pi_n + tau_n
        ull vp  = fma2(kneg2, pi_c, u);       // tau_n - pi_n  (exact -2*pi_c)
        ull t2  = mul2(kp1, pi_p);            // -((n+1)/n)*pi_{n-1}
        ull pin = fma2(kp2, pcc, t2);         // pi_{n+1}

        T1r = fma2(a.x, u, T1r);
        T1i = fma2(a.y, u, T1i);
        T2r = fma2(b.x, vp, T2r);             // accumulates -(Q*(pi-tau));
        T2i = fma2(b.y, vp, T2i);             // sign dies in |T2|^2

        pi_p = pi_c;
        pi_c = pin;
    }

    // (|S1|^2 + |S2|^2)/2 == |T1|^2 + |T2|^2 ; then * wl^2/(4 pi^2)
    ull I = fma2(T1r, T1r, fma2(T1i, T1i, fma2(T2r, T2r, mul2(T2i, T2i))));
    const float SCALE = (float)(3.0249999999999994e-13 / 39.47841760435743);
    return mul2(I, splat2(SCALE));
}

// ---------------- K3: 2 elements per thread ----------------
__global__ void __launch_bounds__(256)
intensity_kernel(const float* __restrict__ theta, float* __restrict__ out, int n) {
    __shared__ __align__(16) ull sh_tab[NMAX * 4];
    int t = threadIdx.x;
    if (t < NMAX * 4) sh_tab[t] = g_tab[t];
    __syncthreads();

    int pairs = n >> 1;
    int i = blockIdx.x * 256 + t;
    if (i < pairs) {
        ull th2 = ((const ull*)theta)[i];
        ((ull*)out)[i] = mie_pair(th2, sh_tab);
    }
    // odd tail (not hit for 8*768*768, kept for safety)
    if ((n & 1) && i == 0) {
        ull th2 = splat2(theta[n - 1]);
        out[n - 1] = lane0(mie_pair(th2, sh_tab));
    }
}

extern "C" void kernel_launch(void* const* d_in, const int* in_sizes, int n_in,
                              void* d_out, int out_size) {
    const float* d_diam  = (const float*)d_in[0];
    const float* d_theta = (const float*)d_in[1];
    float* out = (float*)d_out;
    int n = in_sizes[0];

    reduce_kernel<<<RED_BLOCKS, RED_THREADS>>>(d_diam, n);
    mie_coef_kernel<<<1, 64>>>(n);
    int pairs = (n >> 1);
    int blocks = (pairs + 255) / 256;
    if (blocks < 1) blocks = 1;
    intensity_kernel<<<blocks, 256>>>(d_theta, out, n);
}